// round 2
// baseline (speedup 1.0000x reference)
#include <cuda_runtime.h>
#include <math.h>

#define TT 32
#define NN 20000
#define FF 128
#define HH 128
#define CC 10
#define NB 32
#define NTHREADS 256

// shared-memory layout (floats)
#define WPAD 132          // weight row pad (conflict-free, 16B aligned)
#define XPAD 36           // x/h tile pad   (conflict-free, 16B aligned)
#define OFF_WIH 0
#define OFF_WHH (128*WPAD)
#define OFF_XS  (2*128*WPAD)
#define OFF_HS  (OFF_XS + 128*XPAD)
#define OFF_DWS (OFF_HS + 128*XPAD)
#define SMEM_FLOATS (OFF_DWS + CC*WPAD)
#define SMEM_BYTES  (SMEM_FLOATS * 4)

// Load X[t] tile (32 rows x 128) into smem transposed [k][r].
__device__ __forceinline__ void load_x_tile(float* __restrict__ xs,
                                            const float* __restrict__ X,
                                            int t, int row0, int tid) {
    const float* base = X + ((long)t * NN + row0) * (long)FF;
    const int r  = tid >> 3;   // 0..31
    const int c0 = tid & 7;    // 0..7
#pragma unroll
    for (int it = 0; it < 4; ++it) {
        const int c4 = c0 + 8 * it;   // 0..31 (float4 column)
        float4 v = *reinterpret_cast<const float4*>(base + r * FF + 4 * c4);
        xs[(4 * c4 + 0) * XPAD + r] = v.x;
        xs[(4 * c4 + 1) * XPAD + r] = v.y;
        xs[(4 * c4 + 2) * XPAD + r] = v.z;
        xs[(4 * c4 + 3) * XPAD + r] = v.w;
    }
}

__global__ void __launch_bounds__(NTHREADS, 1)
grn_kernel(const float* __restrict__ X,
           const float* __restrict__ W_ih,
           const float* __restrict__ W_hh,
           const float* __restrict__ b_ih,
           const float* __restrict__ b_hh,
           const float* __restrict__ ln_g,
           const float* __restrict__ ln_b,
           const float* __restrict__ attn_W,
           const float* __restrict__ attn_b,
           const float* __restrict__ dense_W,
           const float* __restrict__ dense_b,
           float* __restrict__ out)
{
    extern __shared__ float sm[];
    float* sWih = sm + OFF_WIH;   // [k][h], pad WPAD
    float* sWhh = sm + OFF_WHH;
    float* sXS  = sm + OFF_XS;    // [k][r], pad XPAD
    float* sHS  = sm + OFF_HS;
    float* sDW  = sm + OFF_DWS;   // [c][h], pad WPAD

    const int tid   = threadIdx.x;
    const int lane  = tid & 31;
    const int wr    = tid >> 5;       // warp id 0..7 -> rows 4*wr..4*wr+3
    const int cbase = 4 * lane;       // this thread's 4 output columns
    const int rbase = 4 * wr;
    const int row0  = blockIdx.x * NB;

    // ---- load weights transposed into SMEM ----
    for (int idx = tid; idx < 128 * 32; idx += NTHREADS) {
        const int h  = idx >> 5;
        const int c4 = idx & 31;
        float4 wi = reinterpret_cast<const float4*>(W_ih + h * FF)[c4];
        float4 wh = reinterpret_cast<const float4*>(W_hh + h * HH)[c4];
        const int k = 4 * c4;
        sWih[(k + 0) * WPAD + h] = wi.x;
        sWih[(k + 1) * WPAD + h] = wi.y;
        sWih[(k + 2) * WPAD + h] = wi.z;
        sWih[(k + 3) * WPAD + h] = wi.w;
        sWhh[(k + 0) * WPAD + h] = wh.x;
        sWhh[(k + 1) * WPAD + h] = wh.y;
        sWhh[(k + 2) * WPAD + h] = wh.z;
        sWhh[(k + 3) * WPAD + h] = wh.w;
    }
    for (int idx = tid; idx < CC * 32; idx += NTHREADS) {
        const int c  = idx >> 5;
        const int c4 = idx & 31;
        float4 v = reinterpret_cast<const float4*>(dense_W + c * HH)[c4];
        sDW[c * WPAD + 4 * c4 + 0] = v.x;
        sDW[c * WPAD + 4 * c4 + 1] = v.y;
        sDW[c * WPAD + 4 * c4 + 2] = v.z;
        sDW[c * WPAD + 4 * c4 + 3] = v.w;
    }

    // ---- per-lane constants ----
    float g4[4], be4[4], aw4[4], bs4[4];
#pragma unroll
    for (int j = 0; j < 4; ++j) {
        g4[j]  = ln_g[cbase + j];
        be4[j] = ln_b[cbase + j];
        aw4[j] = attn_W[cbase + j];
        bs4[j] = b_ih[cbase + j] + b_hh[cbase + j];
    }
    const float attnb = attn_b[0];
    float db10[CC];
#pragma unroll
    for (int c = 0; c < CC; ++c) db10[c] = dense_b[c];

    // ---- stage X[0], then init h0 = X0 @ W_ih^T + (b_ih + b_hh), NO relu ----
    load_x_tile(sXS, X, 0, row0, tid);
    __syncthreads();
    {
        float acc[4][4];
#pragma unroll
        for (int i = 0; i < 4; ++i)
#pragma unroll
            for (int j = 0; j < 4; ++j) acc[i][j] = 0.f;

        const float* xp = sXS  + rbase;
        const float* wp = sWih + cbase;
#pragma unroll 4
        for (int k = 0; k < 128; ++k) {
            float4 xv = *reinterpret_cast<const float4*>(xp); xp += XPAD;
            float4 wv = *reinterpret_cast<const float4*>(wp); wp += WPAD;
            const float a[4] = {xv.x, xv.y, xv.z, xv.w};
            const float b[4] = {wv.x, wv.y, wv.z, wv.w};
#pragma unroll
            for (int i = 0; i < 4; ++i)
#pragma unroll
                for (int j = 0; j < 4; ++j)
                    acc[i][j] = fmaf(a[i], b[j], acc[i][j]);
        }
#pragma unroll
        for (int i = 0; i < 4; ++i)
#pragma unroll
            for (int j = 0; j < 4; ++j)
                sHS[(cbase + j) * XPAD + rbase + i] = acc[i][j] + bs4[j];
    }

    // ---- online-softmax state ----
    float m4[4], z4[4], A[4][CC];
#pragma unroll
    for (int i = 0; i < 4; ++i) {
        m4[i] = -1e30f;
        z4[i] = 0.f;
#pragma unroll
        for (int c = 0; c < CC; ++c) A[i][c] = 0.f;
    }

    // ---- time loop ----
    for (int t = 0; t < TT; ++t) {
        __syncthreads();   // hs (and xs) writes of previous step visible

        float acc[4][4];
#pragma unroll
        for (int i = 0; i < 4; ++i)
#pragma unroll
            for (int j = 0; j < 4; ++j) acc[i][j] = 0.f;

        const float* xp  = sXS  + rbase;
        const float* hp  = sHS  + rbase;
        const float* wip = sWih + cbase;
        const float* whp = sWhh + cbase;
#pragma unroll 4
        for (int k = 0; k < 128; ++k) {
            float4 xv = *reinterpret_cast<const float4*>(xp);  xp  += XPAD;
            float4 hv = *reinterpret_cast<const float4*>(hp);  hp  += XPAD;
            float4 wi = *reinterpret_cast<const float4*>(wip); wip += WPAD;
            float4 wh = *reinterpret_cast<const float4*>(whp); whp += WPAD;
            const float ax[4] = {xv.x, xv.y, xv.z, xv.w};
            const float ah[4] = {hv.x, hv.y, hv.z, hv.w};
            const float bi[4] = {wi.x, wi.y, wi.z, wi.w};
            const float bh[4] = {wh.x, wh.y, wh.z, wh.w};
#pragma unroll
            for (int i = 0; i < 4; ++i)
#pragma unroll
                for (int j = 0; j < 4; ++j)
                    acc[i][j] = fmaf(ah[i], bh[j], fmaf(ax[i], bi[j], acc[i][j]));
        }

        // h_new = relu(acc + b)   (pre-LayerNorm h is the recurrence carry)
        float v[4][4];
#pragma unroll
        for (int i = 0; i < 4; ++i)
#pragma unroll
            for (int j = 0; j < 4; ++j)
                v[i][j] = fmaxf(acc[i][j] + bs4[j], 0.f);

        __syncthreads();   // everyone done reading hs/xs for this step

#pragma unroll
        for (int i = 0; i < 4; ++i)
#pragma unroll
            for (int j = 0; j < 4; ++j)
                sHS[(cbase + j) * XPAD + rbase + i] = v[i][j];

        if (t + 1 < TT) load_x_tile(sXS, X, t + 1, row0, tid);

        // ---- LayerNorm + attention logit + dense head + online softmax ----
#pragma unroll
        for (int i = 0; i < 4; ++i) {
            float s = v[i][0] + v[i][1] + v[i][2] + v[i][3];
            float q = v[i][0]*v[i][0] + v[i][1]*v[i][1] + v[i][2]*v[i][2] + v[i][3]*v[i][3];
#pragma unroll
            for (int o = 16; o; o >>= 1) {
                s += __shfl_xor_sync(0xffffffffu, s, o);
                q += __shfl_xor_sync(0xffffffffu, q, o);
            }
            const float mu  = s * (1.0f / 128.0f);
            float var = q * (1.0f / 128.0f) - mu * mu;
            const float inv = rsqrtf(fmaxf(var, 0.f) + 1e-5f);

            float y[4];
#pragma unroll
            for (int j = 0; j < 4; ++j)
                y[j] = fmaf((v[i][j] - mu) * inv, g4[j], be4[j]);

            float p[CC + 1];
            p[0] = y[0]*aw4[0] + y[1]*aw4[1] + y[2]*aw4[2] + y[3]*aw4[3];
#pragma unroll
            for (int c = 0; c < CC; ++c) {
                float4 dw = *reinterpret_cast<const float4*>(sDW + c * WPAD + cbase);
                p[c + 1] = y[0]*dw.x + y[1]*dw.y + y[2]*dw.z + y[3]*dw.w;
            }
#pragma unroll
            for (int o = 16; o; o >>= 1) {
#pragma unroll
                for (int u = 0; u < CC + 1; ++u)
                    p[u] += __shfl_xor_sync(0xffffffffu, p[u], o);
            }
            const float st = p[0] + attnb;   // identical across lanes (warp-uniform)
            if (st > m4[i]) {
                const float rr = __expf(m4[i] - st);
                z4[i] = fmaf(z4[i], rr, 1.f);
#pragma unroll
                for (int c = 0; c < CC; ++c)
                    A[i][c] = fmaf(A[i][c], rr, p[c + 1] + db10[c]);
                m4[i] = st;
            } else {
                const float e = __expf(st - m4[i]);
                z4[i] += e;
#pragma unroll
                for (int c = 0; c < CC; ++c)
                    A[i][c] = fmaf(e, p[c + 1] + db10[c], A[i][c]);
            }
        }
    }

    // ---- write output (N, 10). 625*32 == 20000, no tail. ----
#pragma unroll
    for (int i = 0; i < 4; ++i) {
        const int n = row0 + rbase + i;
        const float invz = 1.0f / z4[i];
#pragma unroll
        for (int c = 0; c < CC; ++c)
            if (lane == c) out[n * CC + c] = A[i][c] * invz;
    }
}

extern "C" void kernel_launch(void* const* d_in, const int* in_sizes, int n_in,
                              void* d_out, int out_size)
{
    (void)in_sizes; (void)n_in; (void)out_size;
    cudaFuncSetAttribute(grn_kernel,
                         cudaFuncAttributeMaxDynamicSharedMemorySize,
                         SMEM_BYTES);
    grn_kernel<<<NN / NB, NTHREADS, SMEM_BYTES>>>(
        (const float*)d_in[0],   // X
        (const float*)d_in[1],   // W_ih
        (const float*)d_in[2],   // W_hh
        (const float*)d_in[3],   // b_ih
        (const float*)d_in[4],   // b_hh
        (const float*)d_in[5],   // ln_gamma
        (const float*)d_in[6],   // ln_beta
        (const float*)d_in[7],   // attn_W
        (const float*)d_in[8],   // attn_b
        (const float*)d_in[9],   // dense_W
        (const float*)d_in[10],  // dense_b
        (float*)d_out);
}